// round 6
// baseline (speedup 1.0000x reference)
#include <cuda_runtime.h>
#include <cuda_bf16.h>
#include <math.h>
#include <cstdint>

#define PER    12
#define NHEAD  12
#define NCOL   76          // floats per pred row = 19 float4 = 304 B exactly
#define TILE   128         // rows per CTA (4 warps x 32 rows)
#define TPB    128

#define WARP_PRED_BYTES (32 * NCOL * 4)   // 9728, contiguous in GMEM
#define WARP_ROI_BYTES  (32 * 7 * 4)      // 896,  contiguous in GMEM

__device__ __forceinline__ unsigned smem_u32(const void* p) {
    return (unsigned)__cvta_generic_to_shared(p);
}
__device__ __forceinline__ void cpa16(unsigned dst, const void* src) {
    asm volatile("cp.async.cg.shared.global [%0], [%1], 16;" :: "r"(dst), "l"(src));
}
__device__ __forceinline__ void cpa4(unsigned dst, const void* src) {
    asm volatile("cp.async.ca.shared.global [%0], [%1], 4;" :: "r"(dst), "l"(src));
}

__global__ __launch_bounds__(TPB)
void rpn_decode_kernel(const float* __restrict__ roi,
                       const float* __restrict__ pred,
                       const float* __restrict__ anchor,
                       float* __restrict__ out,
                       int N)
{
    __shared__ __align__(16) float pred_s[TILE * NCOL];   // 38912 B
    __shared__ __align__(16) float roi_s [TILE * 7];      //  3584 B
    __shared__ __align__(8)  uint64_t mbar[4];            // one per warp

    const int tid  = threadIdx.x;
    const int wid  = tid >> 5;
    const int lane = tid & 31;

    const int wrow0 = blockIdx.x * TILE + wid * 32;
    if (wrow0 >= N) return;
    const int wrows = min(32, N - wrow0);

    float* wpred = pred_s + wid * 32 * NCOL;
    float* wroi  = roi_s  + wid * 32 * 7;

    const char* psrc = (const char*)(pred + (size_t)wrow0 * NCOL);  // 16B aligned
    const char* rsrc = (const char*)(roi + (size_t)wrow0 * 7);      // 16B aligned

    if (wrows == 32) {
        // ---- TMA bulk stage-in: 2 copies per warp, private mbarrier ----
        const unsigned mb = smem_u32(&mbar[wid]);
        if (lane == 0) {
            asm volatile("mbarrier.init.shared.b64 [%0], 1;" :: "r"(mb) : "memory");
            asm volatile("fence.proxy.async.shared::cta;" ::: "memory");
        }
        __syncwarp();
        if (lane == 0) {
            asm volatile("mbarrier.arrive.expect_tx.shared.b64 _, [%0], %1;"
                         :: "r"(mb), "r"((unsigned)(WARP_PRED_BYTES + WARP_ROI_BYTES))
                         : "memory");
            asm volatile("cp.async.bulk.shared::cta.global.mbarrier::complete_tx::bytes"
                         " [%0], [%1], %2, [%3];"
                         :: "r"(smem_u32(wpred)), "l"(psrc),
                            "r"((unsigned)WARP_PRED_BYTES), "r"(mb) : "memory");
            asm volatile("cp.async.bulk.shared::cta.global.mbarrier::complete_tx::bytes"
                         " [%0], [%1], %2, [%3];"
                         :: "r"(smem_u32(wroi)), "l"(rsrc),
                            "r"((unsigned)WARP_ROI_BYTES), "r"(mb) : "memory");
        }
        __syncwarp();
        // warp spin-wait, phase 0
        {
            unsigned done;
            do {
                asm volatile("{\n\t.reg .pred p;\n\t"
                             "mbarrier.try_wait.parity.shared.b64 p, [%1], 0, 0x989680;\n\t"
                             "selp.u32 %0, 1, 0, p;\n\t}"
                             : "=r"(done) : "r"(mb) : "memory");
            } while (!done);
        }
        __syncwarp();
    } else {
        // ---- tail warp: cp.async fallback (rows*304 per-row copies) ----
        const unsigned sp = smem_u32(wpred);
        const unsigned sr = smem_u32(wroi);
        for (int i = lane; i < wrows * 19; i += 32)
            cpa16(sp + i * 16, psrc + i * 16);
        for (int i = lane; i < wrows * 7; i += 32)
            cpa4(sr + i * 4, rsrc + i * 4);
        asm volatile("cp.async.commit_group;" ::: "memory");
        asm volatile("cp.async.wait_group 0;" ::: "memory");
        __syncwarp();
    }

    const float a0 = __ldg(anchor + 0);
    const float a1 = __ldg(anchor + 1);
    const float a2 = __ldg(anchor + 2);

    // ---- per-row decode: lane owns row wrow0+lane ----
    if (lane < wrows) {
        const float* p = wpred + lane * NCOL;

        int   xb = 0; float xm = p[0];  float xres = p[24];
        #pragma unroll
        for (int i = 1; i < PER; i++) {
            float v = p[i];
            if (v > xm) { xm = v; xb = i; xres = p[24 + i]; }
        }
        int   zb = 0; float zm = p[12]; float zres = p[36];
        #pragma unroll
        for (int i = 1; i < PER; i++) {
            float v = p[12 + i];
            if (v > zm) { zm = v; zb = i; zres = p[36 + i]; }
        }
        int   rb = 0; float rm = p[49]; float rres = p[61];
        #pragma unroll
        for (int i = 1; i < NHEAD; i++) {
            float v = p[49 + i];
            if (v > rm) { rm = v; rb = i; rres = p[61 + i]; }
        }

        float y_off = p[48];
        float ph = p[73], pw = p[74], pl = p[75];

        float roi_x  = wroi[lane * 7 + 0];
        float roi_y  = wroi[lane * 7 + 1];
        float roi_z  = wroi[lane * 7 + 2];
        float roi_ry = wroi[lane * 7 + 6];

        const float LOC_BIN = 0.5f;
        float pos_x = (float)xb * LOC_BIN + 0.25f - 3.0f + xres * LOC_BIN;
        float pos_z = (float)zb * LOC_BIN + 0.25f - 3.0f + zres * LOC_BIN;
        float pos_y = roi_y + y_off;

        const float TWO_PI = 6.2831853071795864769f;
        const float PI_F   = 3.1415926535897932385f;
        const float APC    = TWO_PI / (float)NHEAD;
        float ry = (float)rb * APC + rres * (APC * 0.5f);
        ry = fmodf(ry, TWO_PI);
        if (ry < 0.0f) ry += TWO_PI;   // jnp floor-mod
        if (ry > PI_F) ry -= TWO_PI;

        float h = fmaf(ph, a0, a0);
        float w = fmaf(pw, a1, a1);
        float l = fmaf(pl, a2, a2);

        float s, c;
        sincosf(roi_ry, &s, &c);       // cos(-x)=c, sin(-x)=-s
        float cn = c, sn = -s;
        float x_rot = pos_x * cn - pos_z * sn;
        float z_rot = pos_x * sn + pos_z * cn;

        // stage results into own row slot (owner already consumed the row)
        float* o = wpred + lane * NCOL;
        o[0] = x_rot + roi_x;
        o[1] = pos_y;
        o[2] = z_rot + roi_z;
        o[3] = h;
        o[4] = w;
        o[5] = l;
        o[6] = ry + roi_ry;
    }
    __syncwarp();

    // ---- warp-local vectorized stage-out: 32 rows x 7 = 56 float4 ----
    if (wrows == 32) {
        float4* obase4 = reinterpret_cast<float4*>(out + (size_t)wrow0 * 7); // 16B aligned
        #pragma unroll
        for (int k = 0; k < 2; k++) {
            int j = lane + 32 * k;          // float4 index, 56 total
            if (j < 56) {
                int e = j * 4;
                float4 v;
                int r0 = e / 7,       c0 = e - r0 * 7;
                int r1 = (e+1) / 7,   c1 = (e+1) - r1 * 7;
                int r2 = (e+2) / 7,   c2 = (e+2) - r2 * 7;
                int r3 = (e+3) / 7,   c3 = (e+3) - r3 * 7;
                v.x = wpred[r0 * NCOL + c0];
                v.y = wpred[r1 * NCOL + c1];
                v.z = wpred[r2 * NCOL + c2];
                v.w = wpred[r3 * NCOL + c3];
                obase4[j] = v;
            }
        }
    } else {
        float* obase = out + (size_t)wrow0 * 7;
        for (int i = lane; i < wrows * 7; i += 32) {
            int r = i / 7, c = i - r * 7;
            obase[i] = wpred[r * NCOL + c];
        }
    }
}

extern "C" void kernel_launch(void* const* d_in, const int* in_sizes, int n_in,
                              void* d_out, int out_size)
{
    const float* roi    = (const float*)d_in[0];   // (N,7)
    const float* pred   = (const float*)d_in[1];   // (N,76)
    const float* anchor = (const float*)d_in[2];   // (3,)
    float* out = (float*)d_out;                    // (N,7)

    int N = in_sizes[0] / 7;
    int blocks = (N + TILE - 1) / TILE;
    rpn_decode_kernel<<<blocks, TPB>>>(roi, pred, anchor, out, N);
}

// round 7
// speedup vs baseline: 1.0006x; 1.0006x over previous
#include <cuda_runtime.h>
#include <cuda_bf16.h>
#include <math.h>

#define PER    12
#define NHEAD  12
#define NCOL   76          // floats per pred row = 19 float4 = 304 B exactly
#define TILE   64          // rows per CTA (2 warps x 32 rows)
#define TPB    64

__device__ __forceinline__ unsigned smem_u32(const void* p) {
    return (unsigned)__cvta_generic_to_shared(p);
}
__device__ __forceinline__ void cpa16(unsigned dst, const void* src) {
    asm volatile("cp.async.cg.shared.global [%0], [%1], 16;" :: "r"(dst), "l"(src));
}
__device__ __forceinline__ void cpa4(unsigned dst, const void* src) {
    asm volatile("cp.async.ca.shared.global [%0], [%1], 4;" :: "r"(dst), "l"(src));
}

__global__ __launch_bounds__(TPB)
void rpn_decode_kernel(const float* __restrict__ roi,
                       const float* __restrict__ pred,
                       const float* __restrict__ anchor,
                       float* __restrict__ out,
                       int N)
{
    __shared__ __align__(16) float pred_s[TILE * NCOL];   // 19456 B
    __shared__ __align__(16) float roi_s [TILE * 7];      //  1792 B  (21248 B total -> 10 CTAs/SM)

    const int tid  = threadIdx.x;
    const int wid  = tid >> 5;
    const int lane = tid & 31;

    // each warp owns 32 consecutive rows; no inter-warp coupling at all
    const int wrow0 = blockIdx.x * TILE + wid * 32;
    if (wrow0 >= N) return;
    const int wrows = min(32, N - wrow0);

    float* wpred = pred_s + wid * 32 * NCOL;
    float* wroi  = roi_s  + wid * 32 * 7;

    // ---- warp-local stage-in via cp.async (own group, own wait) ----
    const char* psrc = (const char*)(pred + (size_t)wrow0 * NCOL);  // 16B aligned
    const unsigned sp = smem_u32(wpred);
    const char* rsrc = (const char*)(roi + (size_t)wrow0 * 7);      // 16B aligned
    const unsigned sr = smem_u32(wroi);

    if (wrows == 32) {
        #pragma unroll
        for (int k = 0; k < 19; k++) {                // 608 float4s / warp
            int idx = lane + 32 * k;
            cpa16(sp + idx * 16, psrc + idx * 16);
        }
        #pragma unroll
        for (int k = 0; k < 2; k++) {                 // 56 float4s / warp
            int idx = lane + 32 * k;
            if (idx < 56)
                cpa16(sr + idx * 16, rsrc + idx * 16);
        }
    } else {
        for (int i = lane; i < wrows * 19; i += 32)   // tail rows: whole float4s
            cpa16(sp + i * 16, psrc + i * 16);
        for (int i = lane; i < wrows * 7; i += 32)
            cpa4(sr + i * 4, rsrc + i * 4);
    }
    asm volatile("cp.async.commit_group;" ::: "memory");

    const float a0 = __ldg(anchor + 0);
    const float a1 = __ldg(anchor + 1);
    const float a2 = __ldg(anchor + 2);

    asm volatile("cp.async.wait_group 0;" ::: "memory");
    __syncwarp();

    // ---- per-row decode: lane owns row wrow0+lane ----
    if (lane < wrows) {
        const float* p = wpred + lane * NCOL;

        int   xb = 0; float xm = p[0];  float xres = p[24];
        #pragma unroll
        for (int i = 1; i < PER; i++) {
            float v = p[i];
            if (v > xm) { xm = v; xb = i; xres = p[24 + i]; }
        }
        int   zb = 0; float zm = p[12]; float zres = p[36];
        #pragma unroll
        for (int i = 1; i < PER; i++) {
            float v = p[12 + i];
            if (v > zm) { zm = v; zb = i; zres = p[36 + i]; }
        }
        int   rb = 0; float rm = p[49]; float rres = p[61];
        #pragma unroll
        for (int i = 1; i < NHEAD; i++) {
            float v = p[49 + i];
            if (v > rm) { rm = v; rb = i; rres = p[61 + i]; }
        }

        float y_off = p[48];
        float ph = p[73], pw = p[74], pl = p[75];

        float roi_x  = wroi[lane * 7 + 0];
        float roi_y  = wroi[lane * 7 + 1];
        float roi_z  = wroi[lane * 7 + 2];
        float roi_ry = wroi[lane * 7 + 6];

        const float LOC_BIN = 0.5f;
        float pos_x = (float)xb * LOC_BIN + 0.25f - 3.0f + xres * LOC_BIN;
        float pos_z = (float)zb * LOC_BIN + 0.25f - 3.0f + zres * LOC_BIN;
        float pos_y = roi_y + y_off;

        const float TWO_PI = 6.2831853071795864769f;
        const float PI_F   = 3.1415926535897932385f;
        const float APC    = TWO_PI / (float)NHEAD;
        float ry = (float)rb * APC + rres * (APC * 0.5f);
        ry = fmodf(ry, TWO_PI);
        if (ry < 0.0f) ry += TWO_PI;   // jnp floor-mod
        if (ry > PI_F) ry -= TWO_PI;

        float h = fmaf(ph, a0, a0);
        float w = fmaf(pw, a1, a1);
        float l = fmaf(pl, a2, a2);

        float s, c;
        sincosf(roi_ry, &s, &c);       // cos(-x)=c, sin(-x)=-s
        float cn = c, sn = -s;
        float x_rot = pos_x * cn - pos_z * sn;
        float z_rot = pos_x * sn + pos_z * cn;

        // stage results into own row slot (owner already consumed the row)
        float* o = wpred + lane * NCOL;
        o[0] = x_rot + roi_x;
        o[1] = pos_y;
        o[2] = z_rot + roi_z;
        o[3] = h;
        o[4] = w;
        o[5] = l;
        o[6] = ry + roi_ry;
    }
    __syncwarp();

    // ---- warp-local vectorized stage-out: 32 rows x 7 = 56 float4 ----
    if (wrows == 32) {
        float4* obase4 = reinterpret_cast<float4*>(out + (size_t)wrow0 * 7); // 16B aligned
        #pragma unroll
        for (int k = 0; k < 2; k++) {
            int j = lane + 32 * k;          // float4 index, 56 total
            if (j < 56) {
                int e = j * 4;
                float4 v;
                int r0 = e / 7,       c0 = e - r0 * 7;
                int r1 = (e+1) / 7,   c1 = (e+1) - r1 * 7;
                int r2 = (e+2) / 7,   c2 = (e+2) - r2 * 7;
                int r3 = (e+3) / 7,   c3 = (e+3) - r3 * 7;
                v.x = wpred[r0 * NCOL + c0];
                v.y = wpred[r1 * NCOL + c1];
                v.z = wpred[r2 * NCOL + c2];
                v.w = wpred[r3 * NCOL + c3];
                obase4[j] = v;
            }
        }
    } else {
        float* obase = out + (size_t)wrow0 * 7;
        for (int i = lane; i < wrows * 7; i += 32) {
            int r = i / 7, c = i - r * 7;
            obase[i] = wpred[r * NCOL + c];
        }
    }
}

extern "C" void kernel_launch(void* const* d_in, const int* in_sizes, int n_in,
                              void* d_out, int out_size)
{
    const float* roi    = (const float*)d_in[0];   // (N,7)
    const float* pred   = (const float*)d_in[1];   // (N,76)
    const float* anchor = (const float*)d_in[2];   // (3,)
    float* out = (float*)d_out;                    // (N,7)

    int N = in_sizes[0] / 7;
    int blocks = (N + TILE - 1) / TILE;
    rpn_decode_kernel<<<blocks, TPB>>>(roi, pred, anchor, out, N);
}

// round 8
// speedup vs baseline: 1.0046x; 1.0040x over previous
#include <cuda_runtime.h>
#include <cuda_bf16.h>
#include <math.h>

#define PER    12
#define NHEAD  12
#define NCOL   76          // floats per pred row = 19 float4 = 304 B exactly
#define TILE   128         // rows per CTA (4 warps x 32 rows)
#define TPB    128

__device__ __forceinline__ unsigned smem_u32(const void* p) {
    return (unsigned)__cvta_generic_to_shared(p);
}
__device__ __forceinline__ void cpa16(unsigned dst, const void* src) {
    asm volatile("cp.async.cg.shared.global [%0], [%1], 16;" :: "r"(dst), "l"(src));
}

__global__ __launch_bounds__(TPB)
void rpn_decode_kernel(const float* __restrict__ roi,
                       const float* __restrict__ pred,
                       const float* __restrict__ anchor,
                       float* __restrict__ out,
                       int N)
{
    __shared__ __align__(16) float pred_s[TILE * NCOL];   // 38912 B only

    const int tid  = threadIdx.x;
    const int wid  = tid >> 5;
    const int lane = tid & 31;

    // each warp owns 32 consecutive rows; no inter-warp coupling at all
    const int wrow0 = blockIdx.x * TILE + wid * 32;
    if (wrow0 >= N) return;
    const int wrows = min(32, N - wrow0);

    float* wpred = pred_s + wid * 32 * NCOL;

    // ---- warp-local pred stage-in via cp.async (own group, own wait) ----
    const char* psrc = (const char*)(pred + (size_t)wrow0 * NCOL);  // 16B aligned
    const unsigned sp = smem_u32(wpred);

    if (wrows == 32) {
        #pragma unroll
        for (int k = 0; k < 19; k++) {                // 608 float4s / warp
            int idx = lane + 32 * k;
            cpa16(sp + idx * 16, psrc + idx * 16);
        }
    } else {
        for (int i = lane; i < wrows * 19; i += 32)   // tail rows: whole float4s
            cpa16(sp + i * 16, psrc + i * 16);
    }
    asm volatile("cp.async.commit_group;" ::: "memory");

    // ---- roi fields + anchor straight to registers, overlapping the cp.async ----
    float roi_x = 0.f, roi_y = 0.f, roi_z = 0.f, roi_ry = 0.f;
    if (lane < wrows) {
        const float* rp = roi + (size_t)(wrow0 + lane) * 7;
        roi_x  = __ldg(rp + 0);
        roi_y  = __ldg(rp + 1);
        roi_z  = __ldg(rp + 2);
        roi_ry = __ldg(rp + 6);
    }
    const float a0 = __ldg(anchor + 0);
    const float a1 = __ldg(anchor + 1);
    const float a2 = __ldg(anchor + 2);

    // sincos / rotation terms depend only on roi_ry -> compute before the wait
    float s, c;
    sincosf(roi_ry, &s, &c);           // cos(-x)=c, sin(-x)=-s
    const float cn = c, sn = -s;

    asm volatile("cp.async.wait_group 0;" ::: "memory");
    __syncwarp();

    // ---- per-row decode: lane owns row wrow0+lane ----
    if (lane < wrows) {
        const float* p = wpred + lane * NCOL;

        int   xb = 0; float xm = p[0];  float xres = p[24];
        #pragma unroll
        for (int i = 1; i < PER; i++) {
            float v = p[i];
            if (v > xm) { xm = v; xb = i; xres = p[24 + i]; }
        }
        int   zb = 0; float zm = p[12]; float zres = p[36];
        #pragma unroll
        for (int i = 1; i < PER; i++) {
            float v = p[12 + i];
            if (v > zm) { zm = v; zb = i; zres = p[36 + i]; }
        }
        int   rb = 0; float rm = p[49]; float rres = p[61];
        #pragma unroll
        for (int i = 1; i < NHEAD; i++) {
            float v = p[49 + i];
            if (v > rm) { rm = v; rb = i; rres = p[61 + i]; }
        }

        float y_off = p[48];
        float ph = p[73], pw = p[74], pl = p[75];

        const float LOC_BIN = 0.5f;
        float pos_x = (float)xb * LOC_BIN + 0.25f - 3.0f + xres * LOC_BIN;
        float pos_z = (float)zb * LOC_BIN + 0.25f - 3.0f + zres * LOC_BIN;
        float pos_y = roi_y + y_off;

        const float TWO_PI = 6.2831853071795864769f;
        const float PI_F   = 3.1415926535897932385f;
        const float APC    = TWO_PI / (float)NHEAD;
        float ry = (float)rb * APC + rres * (APC * 0.5f);
        ry = fmodf(ry, TWO_PI);
        if (ry < 0.0f) ry += TWO_PI;   // jnp floor-mod
        if (ry > PI_F) ry -= TWO_PI;

        float h = fmaf(ph, a0, a0);
        float w = fmaf(pw, a1, a1);
        float l = fmaf(pl, a2, a2);

        float x_rot = pos_x * cn - pos_z * sn;
        float z_rot = pos_x * sn + pos_z * cn;

        // stage results into own row slot (owner already consumed the row)
        float* o = wpred + lane * NCOL;
        o[0] = x_rot + roi_x;
        o[1] = pos_y;
        o[2] = z_rot + roi_z;
        o[3] = h;
        o[4] = w;
        o[5] = l;
        o[6] = ry + roi_ry;
    }
    __syncwarp();

    // ---- warp-local vectorized stage-out: 32 rows x 7 = 56 float4 ----
    if (wrows == 32) {
        float4* obase4 = reinterpret_cast<float4*>(out + (size_t)wrow0 * 7); // 16B aligned
        #pragma unroll
        for (int k = 0; k < 2; k++) {
            int j = lane + 32 * k;          // float4 index, 56 total
            if (j < 56) {
                int e = j * 4;
                float4 v;
                int r0 = e / 7,       c0 = e - r0 * 7;
                int r1 = (e+1) / 7,   c1 = (e+1) - r1 * 7;
                int r2 = (e+2) / 7,   c2 = (e+2) - r2 * 7;
                int r3 = (e+3) / 7,   c3 = (e+3) - r3 * 7;
                v.x = wpred[r0 * NCOL + c0];
                v.y = wpred[r1 * NCOL + c1];
                v.z = wpred[r2 * NCOL + c2];
                v.w = wpred[r3 * NCOL + c3];
                obase4[j] = v;
            }
        }
    } else {
        float* obase = out + (size_t)wrow0 * 7;
        for (int i = lane; i < wrows * 7; i += 32) {
            int r = i / 7, c = i - r * 7;
            obase[i] = wpred[r * NCOL + c];
        }
    }
}

extern "C" void kernel_launch(void* const* d_in, const int* in_sizes, int n_in,
                              void* d_out, int out_size)
{
    const float* roi    = (const float*)d_in[0];   // (N,7)
    const float* pred   = (const float*)d_in[1];   // (N,76)
    const float* anchor = (const float*)d_in[2];   // (3,)
    float* out = (float*)d_out;                    // (N,7)

    int N = in_sizes[0] / 7;
    int blocks = (N + TILE - 1) / TILE;
    rpn_decode_kernel<<<blocks, TPB>>>(roi, pred, anchor, out, N);
}